// round 8
// baseline (speedup 1.0000x reference)
#include <cuda_runtime.h>
#include <stdint.h>

// HierarchicalRingTopK: 3x3x3 VALID conv (120 ch) + 4-level gated top-k keep.
// x: (8,3,256,256) f32, w: (120,3,3,3) f32, b: (120,) f32 -> out: (8,120,254,254) f32
//
// FROZEN NUMERICS (rel_err == 0.0 since R4): per-channel serial fp32 FMA chain
// over 27 taps in NHWC patch order (kh, kw, c innermost) from 0, bias added as
// a separate fp32 add. Keys rotl(bits,1). Top-k: magnitude strict-> scan,
// lower index wins ties. f32x2 lanes are independent rn-FMAs (bit-identical).
//
// R7: 2 pixels/thread, BT=64 (pixels base+t and base+64+t, both coalesced).
// Channel-pair f32x2 chains (lanes = ch0,ch1) exactly as R6; each weight-pair
// load (14 LDS.128) now feeds TWO chains (pixel A and pixel B) via duplicated
// per-pixel window registers -> weight shared-mem traffic (the dominant L1
// consumer, ~58% of wavefronts) halves per pixel. sEnc: 2x64 key columns.

#define BT 64
#define OH 254
#define OW 254
#define PLANE (OH * OW)          // 64516
#define NPIX (8 * PLANE)         // 516128
#define NCH 120
#define NPAIR (NCH / 2)          // 60

__device__ __forceinline__ unsigned long long ffma2(unsigned long long a,
                                                    unsigned long long bb_,
                                                    unsigned long long c) {
    unsigned long long d;
    asm("fma.rn.f32x2 %0, %1, %2, %3;" : "=l"(d) : "l"(a), "l"(bb_), "l"(c));
    return d;
}
__device__ __forceinline__ unsigned long long pack2(float lo, float hi) {
    unsigned long long r;
    asm("mov.b64 %0, {%1, %2};" : "=l"(r) : "f"(lo), "f"(hi));
    return r;
}
__device__ __forceinline__ void unpack2(unsigned long long v, float& lo, float& hi) {
    asm("mov.b64 {%0, %1}, %2;" : "=f"(lo), "=f"(hi) : "l"(v));
}

__global__ void __launch_bounds__(BT, 4)
hrtk_kernel(const float* __restrict__ x,
            const float* __restrict__ w,
            const float* __restrict__ b,
            float* __restrict__ out)
{
    // Pair-interleaved weights: wsh2[pr*56 + 2q+e] = w[2pr+e][q]; +54/+55 = biases.
    __shared__ float    wsh2[NPAIR * 56];        // 13440 B
    __shared__ unsigned sEnc[2 * 64 * BT];       // 32768 B (2 pixels x 64 keys)

    const int t = threadIdx.x;

    for (int q = t; q < NPAIR * 56; q += BT) {
        const int pr = q / 56;
        const int r  = q - pr * 56;
        wsh2[q] = (r < 54) ? w[(pr * 2 + (r & 1)) * 27 + (r >> 1)]
                           : b[pr * 2 + (r - 54)];
    }
    __syncthreads();

    const int pbase = blockIdx.x * (BT * 2);
    const int pA = pbase + t;
    const int pB = pbase + BT + t;
    if (pA >= NPIX) return;            // tail: warp1 exits whole, warp0 fully live
    const bool vB = (pB < NPIX);       // warp-uniform (tail block: false for all)
    const int pBl = vB ? pB : pA;      // clamped for loads

    // Decode both pixels; duplicated per-pixel window registers (lanes equal).
    unsigned long long winA[27], winB[27];
    float* obP[2];
    {
        const int wwA = pA % OW, rA = pA / OW, hhA = rA % OH, bbA = rA / OH;
        const int wwB = pBl % OW, rB = pBl / OW, hhB = rB % OH, bbB = rB / OH;
        const float* xa = x + (size_t)bbA * (3 * 65536) + hhA * 256 + wwA;
        const float* xc = x + (size_t)bbB * (3 * 65536) + hhB * 256 + wwB;
#pragma unroll
        for (int ci = 0; ci < 3; ci++)
#pragma unroll
            for (int kh = 0; kh < 3; kh++)
#pragma unroll
                for (int kw = 0; kw < 3; kw++) {
                    const int q = ci * 9 + kh * 3 + kw;
                    const int o = ci * 65536 + kh * 256 + kw;
                    const float vA = __ldg(xa + o);
                    const float vBv = __ldg(xc + o);
                    winA[q] = pack2(vA, vA);
                    winB[q] = pack2(vBv, vBv);
                }
        obP[0] = out + (size_t)bbA * (NCH * PLANE) + hhA * OW + wwA;
        obP[1] = out + (size_t)bbB * (NCH * PLANE) + hhB * OW + wwB;
    }

    unsigned long long gate[2] = { ~0ull, ~0ull };
    int base = 0;

#pragma unroll
    for (int lvl = 0; lvl < 4; lvl++) {
        const int n = 8 << lvl;   // 8,16,32,64
        const int k = 2 << lvl;   // 2,4,8,16
        const int G = n >> 3;

        // Warp-union of both pixels' gates (dead-group skip).
        unsigned long long ugate = ~0ull;
        if (lvl > 0) {
            const unsigned long long gab = gate[0] | gate[1];
            unsigned lo = (unsigned)gab, hi = (unsigned)(gab >> 32);
#pragma unroll
            for (int o = 16; o; o >>= 1) {
                lo |= __shfl_xor_sync(0xffffffffu, lo, o);
                hi |= __shfl_xor_sync(0xffffffffu, hi, o);
            }
            ugate = ((unsigned long long)hi << 32) | lo;
        }

        unsigned gmag[2][8];
#pragma unroll
        for (int g = 0; g < 8; g++) { gmag[0][g] = 0u; gmag[1][g] = 0u; }

        // ---- conv + encode + zero-prefill + group-max build ----
#pragma unroll
        for (int g = 0; g < G; g++) {
            const int ib = g << 3;
            if (((ugate >> ib) & 0xFFull) == 0ull) {
#pragma unroll
                for (int j = 0; j < 8; j++) {
                    sEnc[(0 * 64 + ib + j) * BT + t] = 0u;
                    sEnc[(1 * 64 + ib + j) * BT + t] = 0u;
                    obP[0][(base + ib + j) * PLANE] = 0.0f;
                    if (vB) obP[1][(base + ib + j) * PLANE] = 0.0f;
                }
                continue;
            }
            unsigned gmA = 0u, gmB = 0u;
#pragma unroll
            for (int j2 = 0; j2 < 4; j2++) {
                const int i0 = ib + j2 * 2;
                const int pr = (base + i0) >> 1;
                const float4* wv = (const float4*)(wsh2 + pr * 56);
                float wrp[56];
#pragma unroll
                for (int z = 0; z < 14; z++) *(float4*)&wrp[4 * z] = wv[z];

                // FROZEN Eigen/NHWC tap order; lanes = (ch0,ch1); one weight
                // load feeds both pixels' chains (A and B, independent ILP).
                unsigned long long accA = 0ull, accB = 0ull;
#pragma unroll
                for (int kh = 0; kh < 3; kh++)
#pragma unroll
                    for (int kw = 0; kw < 3; kw++)
#pragma unroll
                        for (int ci = 0; ci < 3; ci++) {
                            const int q = ci * 9 + kh * 3 + kw;
                            const unsigned long long wp =
                                *(const unsigned long long*)&wrp[2 * q];
                            accA = ffma2(winA[q], wp, accA);
                            accB = ffma2(winB[q], wp, accB);
                        }
                float aA0, aA1, aB0, aB1;
                unpack2(accA, aA0, aA1);
                unpack2(accB, aB0, aB1);
                const float actA0 = aA0 + wrp[54];
                const float actA1 = aA1 + wrp[55];
                const float actB0 = aB0 + wrp[54];
                const float actB1 = aB1 + wrp[55];

                const unsigned bA0 = __float_as_uint(actA0);
                const unsigned bA1 = __float_as_uint(actA1);
                const unsigned bB0 = __float_as_uint(actB0);
                const unsigned bB1 = __float_as_uint(actB1);
                unsigned kA0 = __funnelshift_l(bA0, bA0, 1);
                unsigned kA1 = __funnelshift_l(bA1, bA1, 1);
                unsigned kB0 = __funnelshift_l(bB0, bB0, 1);
                unsigned kB1 = __funnelshift_l(bB1, bB1, 1);
                kA0 = ((unsigned)(gate[0] >> (i0    )) & 1u) ? kA0 : 0u;
                kA1 = ((unsigned)(gate[0] >> (i0 + 1)) & 1u) ? kA1 : 0u;
                kB0 = ((unsigned)(gate[1] >> (i0    )) & 1u) ? kB0 : 0u;
                kB1 = ((unsigned)(gate[1] >> (i0 + 1)) & 1u) ? kB1 : 0u;
                sEnc[(0 * 64 + i0    ) * BT + t] = kA0;
                sEnc[(0 * 64 + i0 + 1) * BT + t] = kA1;
                sEnc[(1 * 64 + i0    ) * BT + t] = kB0;
                sEnc[(1 * 64 + i0 + 1) * BT + t] = kB1;
                obP[0][(base + i0    ) * PLANE] = 0.0f;
                obP[0][(base + i0 + 1) * PLANE] = 0.0f;
                if (vB) {
                    obP[1][(base + i0    ) * PLANE] = 0.0f;
                    obP[1][(base + i0 + 1) * PLANE] = 0.0f;
                }
                const unsigned umA0 = kA0 >> 1, umA1 = kA1 >> 1;
                const unsigned umB0 = kB0 >> 1, umB1 = kB1 >> 1;
                if (umA0 > gmA) gmA = umA0;     // ascending: first-wins kept
                if (umA1 > gmA) gmA = umA1;
                if (umB0 > gmB) gmB = umB0;
                if (umB1 > gmB) gmB = umB1;
            }
            gmag[0][g] = gmA;
            gmag[1][g] = gmB;
        }

        // ---- k extractions per pixel: register group-max + 8-slot rescan ----
#pragma unroll
        for (int pp = 0; pp < 2; pp++) {
            unsigned long long selmask = 0ull;
#pragma unroll 1
            for (int s = 0; s < k; s++) {
                unsigned bm = 0u;
                int bg = 0;
#pragma unroll
                for (int g = 0; g < 8; g++)
                    if (g < G && gmag[pp][g] > bm) { bm = gmag[pp][g]; bg = g; }
                if (!bm) break;

                unsigned m2 = 0u, ufull = 0u, found = 0u;
                int leaf = 0;
                const int gb = bg << 3;
#pragma unroll
                for (int j = 0; j < 8; j++) {
                    const unsigned u = sEnc[(pp * 64 + gb + j) * BT + t];
                    const unsigned um = u >> 1;
                    if (um == bm && !found) { found = 1u; leaf = j; ufull = u; }
                    else if (um > m2) m2 = um;
                }
                const int mi = gb + leaf;
                if (pp == 0 || vB)
                    obP[pp][(base + mi) * PLANE] =
                        __uint_as_float(__funnelshift_r(ufull, ufull, 1));
                sEnc[(pp * 64 + mi) * BT + t] = 0u;
#pragma unroll
                for (int g = 0; g < 8; g++)
                    if (g == bg) gmag[pp][g] = m2;
                selmask |= 1ull << mi;
            }

            if (lvl < 3) {
                unsigned long long gg = 0ull;
                unsigned sm2 = (unsigned)selmask;
                while (sm2) {
                    const int j = __ffs(sm2) - 1;
                    sm2 &= sm2 - 1;
                    gg |= 0xFull << (2 * j);
                    if (2 * j + 3 > 63)
                        gg |= 0xFull >> (64 - 2 * j);
                }
                const int Wn = n * 2;
                if (Wn < 64)
                    gg = (gg | (gg >> Wn)) & ((1ull << Wn) - 1ull);
                gate[pp] = gg;
            }
        }
        base += n;
    }
}

extern "C" void kernel_launch(void* const* d_in, const int* in_sizes, int n_in,
                              void* d_out, int out_size)
{
    const float* x = (const float*)d_in[0];
    const float* w = (const float*)d_in[1];
    const float* b = (const float*)d_in[2];
    float* out = (float*)d_out;

    const int grid = (NPIX + BT * 2 - 1) / (BT * 2);
    hrtk_kernel<<<grid, BT>>>(x, w, b, out);
}

// round 9
// speedup vs baseline: 1.1660x; 1.1660x over previous
#include <cuda_runtime.h>
#include <stdint.h>

// HierarchicalRingTopK: 3x3x3 VALID conv (120 ch) + 4-level gated top-k keep.
// x: (8,3,256,256) f32, w: (120,3,3,3) f32, b: (120,) f32 -> out: (8,120,254,254) f32
//
// FROZEN NUMERICS (rel_err == 0.0 since R4): per-channel serial fp32 FMA chain
// over 27 taps in NHWC patch order (kh, kw, c innermost) from 0, bias added as
// a separate fp32 add. Keys rotl(bits,1). Top-k: magnitude strict-> scan,
// lower index wins ties. f32x2 lanes are independent rn-FMAs (bit-identical).
//
// R8: R7 dataflow (2 pixels/thread, channel-pair f32x2 chains, one weight load
// feeds both pixels) but occupancy restored: BT=192 + dynamic smem 111,744B
// -> 2 CTAs/SM = 12 warps, 768 pixels in flight (R6/R7 had 512). Selection
// interleaves pixel A/B extraction (ILP 2 on the LDS-latency chains) and the
// gating mask is built branch-free via bit-spread.

#define BT 192
#define OH 254
#define OW 254
#define PLANE (OH * OW)          // 64516
#define NPIX (8 * PLANE)         // 516128
#define NCH 120
#define NPAIR (NCH / 2)          // 60
#define WBYTES (NPAIR * 56 * 4)                  // 13440
#define SMEM_TOTAL (WBYTES + 2 * 64 * BT * 4)    // 13440 + 98304 = 111744

__device__ __forceinline__ unsigned long long ffma2(unsigned long long a,
                                                    unsigned long long bb_,
                                                    unsigned long long c) {
    unsigned long long d;
    asm("fma.rn.f32x2 %0, %1, %2, %3;" : "=l"(d) : "l"(a), "l"(bb_), "l"(c));
    return d;
}
__device__ __forceinline__ unsigned long long pack2(float lo, float hi) {
    unsigned long long r;
    asm("mov.b64 %0, {%1, %2};" : "=l"(r) : "f"(lo), "f"(hi));
    return r;
}
__device__ __forceinline__ void unpack2(unsigned long long v, float& lo, float& hi) {
    asm("mov.b64 {%0, %1}, %2;" : "=f"(lo), "=f"(hi) : "l"(v));
}

// Gating: selected j -> enable bits 2j..2j+3 (mod 2n). Branch-free bit-spread.
// Matches the original per-bit loop incl. the j==31 wrap (targets 64,65 -> 0,1).
__device__ __forceinline__ unsigned long long gate_from_sel(unsigned m, int n) {
    unsigned long long xv = m;
    xv = (xv | (xv << 16)) & 0x0000FFFF0000FFFFull;
    xv = (xv | (xv << 8 )) & 0x00FF00FF00FF00FFull;
    xv = (xv | (xv << 4 )) & 0x0F0F0F0F0F0F0F0Full;
    xv = (xv | (xv << 2 )) & 0x3333333333333333ull;
    xv = (xv | (xv << 1 )) & 0x5555555555555555ull;     // bit j -> bit 2j
    unsigned long long gg = xv | (xv << 1) | (xv << 2) | (xv << 3);
    if (n == 32 && (m >> 31)) gg |= 0x3ull;             // wrap of j=31
    const int Wn = n * 2;
    if (Wn < 64)
        gg = (gg | (gg >> Wn)) & ((1ull << Wn) - 1ull);
    return gg;
}

__global__ void __launch_bounds__(BT, 2)
hrtk_kernel(const float* __restrict__ x,
            const float* __restrict__ w,
            const float* __restrict__ b,
            float* __restrict__ out)
{
    extern __shared__ unsigned char smemRaw[];
    float*    wsh2 = (float*)smemRaw;                    // pair-interleaved weights
    unsigned* sEnc = (unsigned*)(smemRaw + WBYTES);      // 2 pixels x 64 key columns

    const int t = threadIdx.x;

    // wsh2[pr*56 + 2q+e] = w[2pr+e][q]; +54/+55 = biases.
    for (int q = t; q < NPAIR * 56; q += BT) {
        const int pr = q / 56;
        const int r  = q - pr * 56;
        wsh2[q] = (r < 54) ? w[(pr * 2 + (r & 1)) * 27 + (r >> 1)]
                           : b[pr * 2 + (r - 54)];
    }
    __syncthreads();

    const int pbase = blockIdx.x * (BT * 2);
    const int pA = pbase + t;
    const int pB = pbase + BT + t;
    if (pA >= NPIX) return;            // tail: only warp0 of last block survives
    const bool vB = (pB < NPIX);       // warp-uniform by construction
    const int pBl = vB ? pB : pA;

    unsigned long long winA[27], winB[27];
    float* obP[2];
    {
        const int wwA = pA % OW, rA = pA / OW, hhA = rA % OH, bbA = rA / OH;
        const int wwB = pBl % OW, rB = pBl / OW, hhB = rB % OH, bbB = rB / OH;
        const float* xa = x + (size_t)bbA * (3 * 65536) + hhA * 256 + wwA;
        const float* xc = x + (size_t)bbB * (3 * 65536) + hhB * 256 + wwB;
#pragma unroll
        for (int ci = 0; ci < 3; ci++)
#pragma unroll
            for (int kh = 0; kh < 3; kh++)
#pragma unroll
                for (int kw = 0; kw < 3; kw++) {
                    const int q = ci * 9 + kh * 3 + kw;
                    const int o = ci * 65536 + kh * 256 + kw;
                    const float vA = __ldg(xa + o);
                    const float vC = __ldg(xc + o);
                    winA[q] = pack2(vA, vA);
                    winB[q] = pack2(vC, vC);
                }
        obP[0] = out + (size_t)bbA * (NCH * PLANE) + hhA * OW + wwA;
        obP[1] = out + (size_t)bbB * (NCH * PLANE) + hhB * OW + wwB;
    }

    unsigned long long gate[2] = { ~0ull, ~0ull };
    int base = 0;

#pragma unroll
    for (int lvl = 0; lvl < 4; lvl++) {
        const int n = 8 << lvl;   // 8,16,32,64
        const int k = 2 << lvl;   // 2,4,8,16
        const int G = n >> 3;

        // Warp-union of both pixels' gates (dead-group skip).
        unsigned long long ugate = ~0ull;
        if (lvl > 0) {
            const unsigned long long gab = gate[0] | gate[1];
            unsigned lo = (unsigned)gab, hi = (unsigned)(gab >> 32);
#pragma unroll
            for (int o = 16; o; o >>= 1) {
                lo |= __shfl_xor_sync(0xffffffffu, lo, o);
                hi |= __shfl_xor_sync(0xffffffffu, hi, o);
            }
            ugate = ((unsigned long long)hi << 32) | lo;
        }

        unsigned gmag[2][8];
#pragma unroll
        for (int g = 0; g < 8; g++) { gmag[0][g] = 0u; gmag[1][g] = 0u; }

        // ---- conv + encode + zero-prefill + group-max build ----
#pragma unroll
        for (int g = 0; g < G; g++) {
            const int ib = g << 3;
            if (((ugate >> ib) & 0xFFull) == 0ull) {
#pragma unroll
                for (int j = 0; j < 8; j++) {
                    sEnc[(0 * 64 + ib + j) * BT + t] = 0u;
                    sEnc[(1 * 64 + ib + j) * BT + t] = 0u;
                    obP[0][(base + ib + j) * PLANE] = 0.0f;
                    if (vB) obP[1][(base + ib + j) * PLANE] = 0.0f;
                }
                continue;
            }
            unsigned gmA = 0u, gmB = 0u;
#pragma unroll
            for (int j2 = 0; j2 < 4; j2++) {
                const int i0 = ib + j2 * 2;
                const int pr = (base + i0) >> 1;
                const float4* wv = (const float4*)(wsh2 + pr * 56);
                float wrp[56];
#pragma unroll
                for (int z = 0; z < 14; z++) *(float4*)&wrp[4 * z] = wv[z];

                // FROZEN Eigen/NHWC tap order; lanes=(ch0,ch1); one weight
                // load feeds both pixels' chains (independent ILP).
                unsigned long long accA = 0ull, accB = 0ull;
#pragma unroll
                for (int kh = 0; kh < 3; kh++)
#pragma unroll
                    for (int kw = 0; kw < 3; kw++)
#pragma unroll
                        for (int ci = 0; ci < 3; ci++) {
                            const int q = ci * 9 + kh * 3 + kw;
                            const unsigned long long wp =
                                *(const unsigned long long*)&wrp[2 * q];
                            accA = ffma2(winA[q], wp, accA);
                            accB = ffma2(winB[q], wp, accB);
                        }
                float aA0, aA1, aB0, aB1;
                unpack2(accA, aA0, aA1);
                unpack2(accB, aB0, aB1);
                const float actA0 = aA0 + wrp[54];
                const float actA1 = aA1 + wrp[55];
                const float actB0 = aB0 + wrp[54];
                const float actB1 = aB1 + wrp[55];

                const unsigned bA0 = __float_as_uint(actA0);
                const unsigned bA1 = __float_as_uint(actA1);
                const unsigned bB0 = __float_as_uint(actB0);
                const unsigned bB1 = __float_as_uint(actB1);
                unsigned kA0 = __funnelshift_l(bA0, bA0, 1);
                unsigned kA1 = __funnelshift_l(bA1, bA1, 1);
                unsigned kB0 = __funnelshift_l(bB0, bB0, 1);
                unsigned kB1 = __funnelshift_l(bB1, bB1, 1);
                kA0 = ((unsigned)(gate[0] >> (i0    )) & 1u) ? kA0 : 0u;
                kA1 = ((unsigned)(gate[0] >> (i0 + 1)) & 1u) ? kA1 : 0u;
                kB0 = ((unsigned)(gate[1] >> (i0    )) & 1u) ? kB0 : 0u;
                kB1 = ((unsigned)(gate[1] >> (i0 + 1)) & 1u) ? kB1 : 0u;
                sEnc[(0 * 64 + i0    ) * BT + t] = kA0;
                sEnc[(0 * 64 + i0 + 1) * BT + t] = kA1;
                sEnc[(1 * 64 + i0    ) * BT + t] = kB0;
                sEnc[(1 * 64 + i0 + 1) * BT + t] = kB1;
                obP[0][(base + i0    ) * PLANE] = 0.0f;
                obP[0][(base + i0 + 1) * PLANE] = 0.0f;
                if (vB) {
                    obP[1][(base + i0    ) * PLANE] = 0.0f;
                    obP[1][(base + i0 + 1) * PLANE] = 0.0f;
                }
                const unsigned umA0 = kA0 >> 1, umA1 = kA1 >> 1;
                const unsigned umB0 = kB0 >> 1, umB1 = kB1 >> 1;
                if (umA0 > gmA) gmA = umA0;     // ascending: first-wins kept
                if (umA1 > gmA) gmA = umA1;
                if (umB0 > gmB) gmB = umB0;
                if (umB1 > gmB) gmB = umB1;
            }
            gmag[0][g] = gmA;
            gmag[1][g] = gmB;
        }

        // ---- k extractions, pixels A/B interleaved (2 independent chains) ----
        unsigned selA = 0u;
        unsigned long long selB = 0ull;
#pragma unroll 1
        for (int s = 0; s < k; s++) {
            unsigned bmA = 0u, bmB = 0u;
            int bgA = 0, bgB = 0;
#pragma unroll
            for (int g = 0; g < 8; g++) {
                if (g < G) {
                    if (gmag[0][g] > bmA) { bmA = gmag[0][g]; bgA = g; }
                    if (gmag[1][g] > bmB) { bmB = gmag[1][g]; bgB = g; }
                }
            }
            if (!(bmA | bmB)) break;

            const int gbA = bgA << 3, gbB = bgB << 3;
            unsigned uA[8], uB[8];
#pragma unroll
            for (int j = 0; j < 8; j++) uA[j] = sEnc[(0 * 64 + gbA + j) * BT + t];
#pragma unroll
            for (int j = 0; j < 8; j++) uB[j] = sEnc[(1 * 64 + gbB + j) * BT + t];

            if (bmA) {
                unsigned m2 = 0u, ufull = 0u, found = 0u;
                int leaf = 0;
#pragma unroll
                for (int j = 0; j < 8; j++) {
                    const unsigned um = uA[j] >> 1;
                    if (um == bmA && !found) { found = 1u; leaf = j; ufull = uA[j]; }
                    else if (um > m2) m2 = um;
                }
                const int mi = gbA + leaf;
                obP[0][(base + mi) * PLANE] =
                    __uint_as_float(__funnelshift_r(ufull, ufull, 1));
                sEnc[(0 * 64 + mi) * BT + t] = 0u;
#pragma unroll
                for (int g = 0; g < 8; g++)
                    if (g == bgA) gmag[0][g] = m2;
                selA |= 1u << mi;
            }
            if (bmB) {
                unsigned m2 = 0u, ufull = 0u, found = 0u;
                int leaf = 0;
#pragma unroll
                for (int j = 0; j < 8; j++) {
                    const unsigned um = uB[j] >> 1;
                    if (um == bmB && !found) { found = 1u; leaf = j; ufull = uB[j]; }
                    else if (um > m2) m2 = um;
                }
                const int mi = gbB + leaf;
                if (vB)
                    obP[1][(base + mi) * PLANE] =
                        __uint_as_float(__funnelshift_r(ufull, ufull, 1));
                sEnc[(1 * 64 + mi) * BT + t] = 0u;
#pragma unroll
                for (int g = 0; g < 8; g++)
                    if (g == bgB) gmag[1][g] = m2;
                selB |= 1ull << mi;
            }
        }

        if (lvl < 3) {
            gate[0] = gate_from_sel(selA, n);
            gate[1] = gate_from_sel((unsigned)selB, n);
        }
        base += n;
    }
}

extern "C" void kernel_launch(void* const* d_in, const int* in_sizes, int n_in,
                              void* d_out, int out_size)
{
    const float* x = (const float*)d_in[0];
    const float* w = (const float*)d_in[1];
    const float* b = (const float*)d_in[2];
    float* out = (float*)d_out;

    cudaFuncSetAttribute(hrtk_kernel,
                         cudaFuncAttributeMaxDynamicSharedMemorySize, SMEM_TOTAL);
    const int grid = (NPIX + BT * 2 - 1) / (BT * 2);
    hrtk_kernel<<<grid, BT, SMEM_TOTAL>>>(x, w, b, out);
}